// round 10
// baseline (speedup 1.0000x reference)
#include <cuda_runtime.h>
#include <cuda_bf16.h>
#include <math.h>
#include <stdint.h>

// Problem constants: B=64, T=512, V=32000, E=256, H=512, 4H=2048, NT=12, C=10
#define NBLK 128          // persistent LSTM blocks (<=148 SMs -> co-resident)
#define PADTAG 0
#define BOS 10
#define EOSx 11

// ---------------- scratch: static device memory (no runtime allocs) ----------
// X layout: [dir][ (t*2048 + g*512+u) * 64 + b ]  (b innermost -> coalesced)
__device__ float    g_X[2][67108864];
// hid layout: [ (dir*512+u) * 32768 + t*64 + b ]  (coalesced LSTM stores)
__device__ float    g_hid[33554432];
__device__ float    g_h[2 * 3 * 512 * 64]; // [dir][buf][k4][b][4] packed carry ring
__device__ float    g_hT[64 * 1024];       // [b][dir*512+u] final carry
__device__ float    g_emis[32768 * 12];    // [(t*64+b)*12 + tag]
__device__ unsigned g_bar2[64];            // per-dir counters at [0] and [16]

// ---------------- f32x2 packed-FMA helpers (sm_103a) -------------------------
union U64F2 { unsigned long long u; float2 f2; };
union F4U2  { float4 f4; unsigned long long u2[2]; };

__device__ __forceinline__ unsigned long long fma2(unsigned long long a,
                                                   unsigned long long b,
                                                   unsigned long long c) {
    unsigned long long d;
    asm("fma.rn.f32x2 %0, %1, %2, %3;" : "=l"(d) : "l"(a), "l"(b), "l"(c));
    return d;
}
__device__ __forceinline__ unsigned long long splat2(float a) {
    unsigned long long r;
    asm("mov.b64 %0, {%1, %1};" : "=l"(r) : "f"(a));
    return r;
}

// ---------------- XLA-exact activations --------------------------------------
__device__ __forceinline__ float tanh_xla(float x) {
    const float ax = fabsf(x);
    float xc = fminf(fmaxf(x, -9.0f), 9.0f);
    float x2 = __fmul_rn(xc, xc);
    float p = -2.76076847742355e-16f;
    p = __fadd_rn(__fmul_rn(x2, p),  2.00018790482477e-13f);
    p = __fadd_rn(__fmul_rn(x2, p), -8.60467152213735e-11f);
    p = __fadd_rn(__fmul_rn(x2, p),  5.12229709037114e-08f);
    p = __fadd_rn(__fmul_rn(x2, p),  1.48572235717979e-05f);
    p = __fadd_rn(__fmul_rn(x2, p),  6.37261928875436e-04f);
    p = __fadd_rn(__fmul_rn(x2, p),  4.89352455891786e-03f);
    float num = __fmul_rn(xc, p);
    float q = 1.19825839466702e-06f;
    q = __fadd_rn(__fmul_rn(x2, q), 1.18534705686654e-04f);
    q = __fadd_rn(__fmul_rn(x2, q), 2.26843463243900e-03f);
    q = __fadd_rn(__fmul_rn(x2, q), 4.89352518554385e-03f);
    float r = __fdiv_rn(num, q);
    return (ax < 0.0004f) ? x : r;
}
__device__ __forceinline__ float sigmoid_xla(float x) {
    return __fadd_rn(0.5f, __fmul_rn(0.5f, tanh_xla(__fmul_rn(0.5f, x))));
}

// ---------------- init: reset spin-barrier counters every replay -------------
__global__ void init_kernel() {
    if (threadIdx.x < 64) g_bar2[threadIdx.x] = 0u;
}

// ---------------- phase 1: fused embedding gather + input projection GEMM ----
// Tile = (all 64 b) x (fixed t) x (64 n).  out[(t*2048+n)*64+b] = emb[x[b,t]].W[n]
// Accumulator chains identical to previous rounds (bit-exact); only the store
// path changed: stage the 64n x 64b tile through smem, write coalesced float4.
__global__ __launch_bounds__(256) void gemm_ih(const int* __restrict__ x,
                                               const float* __restrict__ emb,
                                               const float* __restrict__ wf,
                                               const float* __restrict__ wb) {
    __shared__ float As[16][64];
    __shared__ float Bs[16][64];
    __shared__ int   rix[64];
    __shared__ float outsm[64][68];        // [n_local][b_local], padded
    const int dir = blockIdx.z;
    const int t0  = blockIdx.y;
    const float* __restrict__ W = dir ? wb : wf;
    float* __restrict__ Xout = g_X[dir];
    const int tid = threadIdx.x;
    const int n0 = blockIdx.x << 6;

    if (tid < 64) rix[tid] = x[tid * 512 + t0];   // x[b][t0]
    __syncthreads();

    const int r  = tid & 63, kk = tid >> 6;       // loader: row r, k-quad kk
    const int tx = tid & 15, ty = tid >> 4;       // compute: 4x4 micro-tile
    const float* aptr = emb + (size_t)rix[r] * 256 + (kk << 2);
    const float* bptr = W   + (size_t)(n0 + r) * 256 + (kk << 2);

    unsigned long long acc[4][2];
#pragma unroll
    for (int i = 0; i < 4; ++i) { acc[i][0] = 0ull; acc[i][1] = 0ull; }

    for (int kt = 0; kt < 16; ++kt) {
        float4 a = *(const float4*)(aptr + (kt << 4));
        float4 b = *(const float4*)(bptr + (kt << 4));
        __syncthreads();
        As[(kk << 2) + 0][r] = a.x; As[(kk << 2) + 1][r] = a.y;
        As[(kk << 2) + 2][r] = a.z; As[(kk << 2) + 3][r] = a.w;
        Bs[(kk << 2) + 0][r] = b.x; Bs[(kk << 2) + 1][r] = b.y;
        Bs[(kk << 2) + 2][r] = b.z; Bs[(kk << 2) + 3][r] = b.w;
        __syncthreads();
#pragma unroll
        for (int k = 0; k < 16; ++k) {
            float4 av = *(const float4*)&As[k][ty << 2];   // b-dim
            F4U2 bu; bu.f4 = *(const float4*)&Bs[k][tx << 2]; // n-dim
            float ar[4] = {av.x, av.y, av.z, av.w};
#pragma unroll
            for (int i = 0; i < 4; ++i) {
                unsigned long long ai = splat2(ar[i]);
                acc[i][0] = fma2(ai, bu.u2[0], acc[i][0]);
                acc[i][1] = fma2(ai, bu.u2[1], acc[i][1]);
            }
        }
    }
    __syncthreads();
    // acc[i][.]: i -> b_local = ty*4+i ; pair lanes -> n_local = tx*4 + {0..3}
#pragma unroll
    for (int i = 0; i < 4; ++i) {
        U64F2 lo, hi; lo.u = acc[i][0]; hi.u = acc[i][1];
        const int bl = (ty << 2) + i, nl = tx << 2;
        outsm[nl + 0][bl] = lo.f2.x;
        outsm[nl + 1][bl] = lo.f2.y;
        outsm[nl + 2][bl] = hi.f2.x;
        outsm[nl + 3][bl] = hi.f2.y;
    }
    __syncthreads();
    for (int idx = tid; idx < 1024; idx += 256) {
        const int nl = idx >> 4, b4 = idx & 15;
        float4 v = *(const float4*)&outsm[nl][b4 << 2];
        __stcs((float4*)(Xout + ((size_t)t0 * 2048 + n0 + nl) * 64 + (b4 << 2)), v);
    }
}

// ---------------- phase 2: persistent bidirectional LSTM ---------------------
// 128 blocks. dir = blk/64; block owns 8 hidden units u0 = (blk%64)*8.
// Per-dir grid barrier (64 blocks). X for the step is prefetched into registers
// BEFORE the barrier so its DRAM latency hides inside the barrier wait.
#define LSTM_SMEM ((32 * 512 + 512 * 64 + 512) * 4)

__device__ __forceinline__ void grid_barrier(unsigned* ctr, unsigned target) {
    __syncthreads();
    if (threadIdx.x == 0) {
        __threadfence();
        atomicAdd(ctr, 1u);
        while (*(volatile unsigned*)ctr < target) __nanosleep(32);
        __threadfence();
    }
    __syncthreads();
}

__global__ __launch_bounds__(256, 1) void lstm_kernel(const int* __restrict__ x,
                                                      const float* __restrict__ whh_f,
                                                      const float* __restrict__ whh_b,
                                                      const float* __restrict__ bias_f,
                                                      const float* __restrict__ bias_b) {
    extern __shared__ float sm[];
    float* Wsm = sm;                       // 32*512
    float* hsm = sm + 32 * 512;            // packed [k4][b][4] (512*64 floats)
    float* csm = hsm + 512 * 64;           // 8*64   ([j*64+b])

    const int tid = threadIdx.x;
    const int blk = blockIdx.x;
    const int dir = blk >> 6;
    const int u0  = (blk & 63) << 3;
    const int b   = tid & 63;
    const int p   = tid >> 6;              // 0..3; thread owns units p, p+4
    const float* __restrict__ Whh = dir ? whh_b : whh_f;
    const float* __restrict__ bia = dir ? bias_b : bias_f;
    const float* __restrict__ Xg  = g_X[dir];
    float* __restrict__ ring = g_h + dir * (3 * 512 * 64);
    unsigned* ctr = &g_bar2[dir * 16];

    // resident weights: local row lr = gate*8 + j  ->  w_hh[gate*512+u0+j][:]
    for (int i = tid; i < 32 * 128; i += 256) {     // float4 granules
        int lr = i >> 7, k4 = (i & 127) << 2;
        int gate = lr >> 3, j = lr & 7;
        float4 v = *(const float4*)&Whh[(size_t)(gate * 512 + u0 + j) * 512 + k4];
        *(float4*)&Wsm[lr * 512 + k4] = v;
    }
    float bb0[4], bb1[4];
#pragma unroll
    for (int g = 0; g < 4; ++g) {
        bb0[g] = bia[g * 512 + u0 + p];
        bb1[g] = bia[g * 512 + u0 + p + 4];
    }
    for (int i = tid; i < 512; i += 256) csm[i] = 0.f;
    // zero ring buffer 0 for own units (packed [k4][b][4] layout)
    for (int i = tid; i < 512; i += 256) {
        int j = i >> 6, bb = i & 63, u = u0 + j;
        ring[((u >> 2) * 64 + bb) * 4 + (u & 3)] = 0.f;
    }
    __threadfence();

    const int u_a = u0 + p, u_b = u0 + p + 4;
    // prefetch X for step 0 (independent of the barrier -> hidden in the wait)
    float xr0[4], xr1[4];
    {
        const int t = dir ? 511 : 0;
        const size_t base = (size_t)t * 131072;   // t*2048*64
#pragma unroll
        for (int g = 0; g < 4; ++g) {
            xr0[g] = __ldcs(&Xg[base + (size_t)(g * 512 + u_a) * 64 + b]);
            xr1[g] = __ldcs(&Xg[base + (size_t)(g * 512 + u_b) * 64 + b]);
        }
    }
    unsigned nbar = 1;
    grid_barrier(ctr, nbar * 64);

    for (int s = 0; s < 512; ++s) {
        const int t  = dir ? 511 - s : s;
        const int rb = s % 3, wbuf = (s + 1) % 3;

        const float4* src4 = (const float4*)(ring + rb * 32768);
        float4* dst4 = (float4*)hsm;
        float4 rreg[8];
#pragma unroll
        for (int q = 0; q < 8; ++q) rreg[q] = __ldcg(src4 + tid + 256 * q);

        unsigned long long d0[4] = {0ull, 0ull, 0ull, 0ull};
        unsigned long long d1[4] = {0ull, 0ull, 0ull, 0ull};

        for (int c = 0; c < 4; ++c) {
#pragma unroll
            for (int q = 0; q < 8; ++q)
                dst4[c * 2048 + tid + 256 * q] = rreg[q];
            if (c < 3) {
#pragma unroll
                for (int q = 0; q < 8; ++q)
                    rreg[q] = __ldcg(src4 + (c + 1) * 2048 + tid + 256 * q);
            }
            __syncthreads();
            const int kbeg = c << 7;
#pragma unroll 4
            for (int k = kbeg; k < kbeg + 128; k += 4) {
                F4U2 h4; h4.f4 = *(const float4*)&hsm[((k >> 2) * 64 + b) * 4];
#pragma unroll
                for (int g = 0; g < 4; ++g) {
                    F4U2 w0; w0.f4 = *(const float4*)&Wsm[(g * 8 + p) * 512 + k];
                    d0[g] = fma2(h4.u2[0], w0.u2[0], d0[g]);
                    d0[g] = fma2(h4.u2[1], w0.u2[1], d0[g]);
                    F4U2 w1; w1.f4 = *(const float4*)&Wsm[(g * 8 + p + 4) * 512 + k];
                    d1[g] = fma2(h4.u2[0], w1.u2[0], d1[g]);
                    d1[g] = fma2(h4.u2[1], w1.u2[1], d1[g]);
                }
            }
        }

        const bool mk = (x[b * 512 + t] != 0);
#pragma unroll
        for (int half = 0; half < 2; ++half) {
            const unsigned long long* dd = half ? d1 : d0;
            const float* bv = half ? bb1 : bb0;
            const float* xr = half ? xr1 : xr0;
            const int j = p + half * 4;
            const int u = u0 + j;
            U64F2 e0, e1, e2, e3;
            e0.u = dd[0]; e1.u = dd[1]; e2.u = dd[2]; e3.u = dd[3];
            float s0 = __fadd_rn(e0.f2.x, e0.f2.y);
            float s1 = __fadd_rn(e1.f2.x, e1.f2.y);
            float s2 = __fadd_rn(e2.f2.x, e2.f2.y);
            float s3 = __fadd_rn(e3.f2.x, e3.f2.y);
            float zi = __fadd_rn(__fadd_rn(xr[0], s0), bv[0]);
            float zf = __fadd_rn(__fadd_rn(xr[1], s1), bv[1]);
            float zg = __fadd_rn(__fadd_rn(xr[2], s2), bv[2]);
            float zo = __fadd_rn(__fadd_rn(xr[3], s3), bv[3]);
            float ii = sigmoid_xla(zi);
            float ff = sigmoid_xla(zf);
            float oo = sigmoid_xla(zo);
            float gg = tanh_xla(zg);
            float cold = csm[j * 64 + b];
            float cn = __fadd_rn(__fmul_rn(ff, cold), __fmul_rn(ii, gg));
            float hn = __fmul_rn(oo, tanh_xla(cn));
            float hold = hsm[((u >> 2) * 64 + b) * 4 + (u & 3)];
            float ck = mk ? cn : cold;
            float hk = mk ? hn : hold;
            csm[j * 64 + b] = ck;
            // coalesced streaming store: [unit][t*64+b]
            __stcs(&g_hid[(size_t)(dir * 512 + u) * 32768 + t * 64 + b],
                   mk ? hn : 0.f);
            ring[wbuf * 32768 + ((u >> 2) * 64 + b) * 4 + (u & 3)] = hk;
            if (s == 511) g_hT[b * 1024 + dir * 512 + u] = hk;
        }
        // prefetch X for next step while waiting on the barrier
        if (s < 511) {
            const int tn = dir ? 510 - s : s + 1;
            const size_t base = (size_t)tn * 131072;
#pragma unroll
            for (int g = 0; g < 4; ++g) {
                xr0[g] = __ldcs(&Xg[base + (size_t)(g * 512 + u_a) * 64 + b]);
                xr1[g] = __ldcs(&Xg[base + (size_t)(g * 512 + u_b) * 64 + b]);
            }
        }
        __threadfence();
        ++nbar;
        grid_barrier(ctr, nbar * 64);
    }
}

// ---------------- phase 3: emissions = hid @ fc_w.T + fc_b -------------------
// Thread per (t,b); hid reads coalesced from [unit][t*64+b]; fc_w in smem.
// FMA-Kahan per term: compensation stream also captures the product rounding.
__global__ __launch_bounds__(256) void emis_kernel(const float* __restrict__ fcw,
                                                   const float* __restrict__ fcb) {
    __shared__ float smw[12 * 1024];
    const int tid = threadIdx.x;
    const int tb  = blockIdx.x * 256 + tid;
    for (int i = tid; i < 12288; i += 256) smw[i] = fcw[i];
    __syncthreads();
    float s[12], c[12];
#pragma unroll
    for (int j = 0; j < 12; ++j) { s[j] = 0.f; c[j] = 0.f; }
#pragma unroll 2
    for (int k = 0; k < 1024; ++k) {
        float hv = __ldcs(&g_hid[(size_t)k * 32768 + tb]);
#pragma unroll
        for (int j = 0; j < 12; ++j) {
            float y = __fmaf_rn(hv, smw[j * 1024 + k], -c[j]);
            float t = __fadd_rn(s[j], y);
            c[j] = __fsub_rn(__fsub_rn(t, s[j]), y);
            s[j] = t;
        }
    }
#pragma unroll
    for (int j = 0; j < 12; ++j) {
        float r = (float)((double)s[j] - (double)c[j]);
        g_emis[(size_t)tb * 12 + j] = __fadd_rn(r, fcb[j]);
    }
}

// ---------------- phase 4: class probs = softmax(hT @ fc2_w.T + fc2_b) -------
__global__ __launch_bounds__(32) void cls_kernel(const float* __restrict__ w2,
                                                 const float* __restrict__ b2,
                                                 float* __restrict__ out) {
    const int bb = blockIdx.x;
    const int lane = threadIdx.x;
    double acc[10];
#pragma unroll
    for (int j = 0; j < 10; ++j) acc[j] = 0.0;
    for (int k = lane; k < 1024; k += 32) {
        double hv = (double)g_hT[bb * 1024 + k];
#pragma unroll
        for (int j = 0; j < 10; ++j)
            acc[j] = fma(hv, (double)__ldg(&w2[j * 1024 + k]), acc[j]);
    }
#pragma unroll
    for (int j = 0; j < 10; ++j)
#pragma unroll
        for (int off = 16; off; off >>= 1)
            acc[j] += __shfl_down_sync(0xffffffffu, acc[j], off);
    if (lane == 0) {
        float z[10], mx = -1e30f, ssum = 0.f;
#pragma unroll
        for (int j = 0; j < 10; ++j) { z[j] = __fadd_rn((float)acc[j], b2[j]); mx = fmaxf(mx, z[j]); }
#pragma unroll
        for (int j = 0; j < 10; ++j) { z[j] = expf(z[j] - mx); ssum += z[j]; }
        float inv = 1.f / ssum;
#pragma unroll
        for (int j = 0; j < 10; ++j) out[64 + 32768 + bb * 10 + j] = z[j] * inv;
    }
}

// ---------------- phase 5: Viterbi — warp-synchronous, shfl-based ------------
__global__ __launch_bounds__(32) void vit_kernel(const int* __restrict__ x,
                                                 const float* __restrict__ trans,
                                                 float* __restrict__ out) {
    const int bb = blockIdx.x;
    const int lane = threadIdx.x;
    __shared__ float tr[144];
    __shared__ short bp[511][12];
    __shared__ short path[512];

    for (int i = lane; i < 144; i += 32) tr[i] = trans[i];
    __syncwarp();

    float tcol[12];
#pragma unroll
    for (int i = 0; i < 12; ++i) tcol[i] = (lane < 12) ? tr[i * 12 + lane] : 0.f;

    float alph = (lane < 12)
        ? __fadd_rn(tr[BOS * 12 + lane], g_emis[(size_t)(0 * 64 + bb) * 12 + lane])
        : -1e30f;

    float e_cur = (lane < 12) ? g_emis[(size_t)(1 * 64 + bb) * 12 + lane] : 0.f;
    int   v_cur = (x[bb * 512 + 1] != 0);

    for (int t = 1; t < 512; ++t) {
        float e_nxt = 0.f; int v_nxt = 0;
        if (t < 511) {
            e_nxt = (lane < 12) ? g_emis[(size_t)((t + 1) * 64 + bb) * 12 + lane] : 0.f;
            v_nxt = (x[bb * 512 + t + 1] != 0);
        }
        float best = -1e30f; int bi = 0;
#pragma unroll
        for (int i = 0; i < 12; ++i) {
            float ai = __shfl_sync(0xffffffffu, alph, i);
            float sc = __fadd_rn(ai, tcol[i]);
            if (sc > best) { best = sc; bi = i; }    // first-index tie-break
        }
        if (lane < 12) {
            alph = v_cur ? __fadd_rn(best, e_cur) : alph;
            bp[t - 1][lane] = v_cur ? (short)bi : (short)lane;
        }
        e_cur = e_nxt; v_cur = v_nxt;
    }
    __syncwarp();

    float fin = -1e30f;
    if (lane < 12) fin = __fadd_rn(alph, tr[lane * 12 + EOSx]);
    float best = -1e30f; int bt = 0;
#pragma unroll
    for (int i = 0; i < 12; ++i) {
        float fi = __shfl_sync(0xffffffffu, fin, i);
        if (fi > best) { best = fi; bt = i; }
    }
    if (lane == 0) {
        out[bb] = best;
        int tag = bt;
        for (int t = 511; t >= 1; --t) { path[t] = (short)tag; tag = bp[t - 1][tag]; }
        path[0] = (short)tag;
    }
    __syncwarp();
    for (int t = lane; t < 512; t += 32)
        out[64 + bb * 512 + t] = (x[bb * 512 + t] != 0) ? (float)path[t] : (float)PADTAG;
}

// ---------------- launcher ---------------------------------------------------
extern "C" void kernel_launch(void* const* d_in, const int* in_sizes, int n_in,
                              void* d_out, int out_size) {
    const int*   x      = (const int*)d_in[0];
    const float* emb    = (const float*)d_in[1];
    const float* w_ih_f = (const float*)d_in[2];
    const float* w_hh_f = (const float*)d_in[3];
    const float* b_f    = (const float*)d_in[4];
    const float* w_ih_b = (const float*)d_in[5];
    const float* w_hh_b = (const float*)d_in[6];
    const float* b_b    = (const float*)d_in[7];
    const float* fc_w   = (const float*)d_in[8];
    const float* fc_b   = (const float*)d_in[9];
    const float* fc2_w  = (const float*)d_in[10];
    const float* fc2_b  = (const float*)d_in[11];
    const float* trans  = (const float*)d_in[12];
    float* out = (float*)d_out;

    cudaFuncSetAttribute(lstm_kernel,
                         cudaFuncAttributeMaxDynamicSharedMemorySize, LSTM_SMEM);

    init_kernel<<<1, 64>>>();
    gemm_ih<<<dim3(32, 512, 2), 256>>>(x, emb, w_ih_f, w_ih_b);
    lstm_kernel<<<NBLK, 256, LSTM_SMEM>>>(x, w_hh_f, w_hh_b, b_f, b_b);
    emis_kernel<<<128, 256>>>(fc_w, fc_b);
    cls_kernel<<<64, 32>>>(fc2_w, fc2_b, out);
    vit_kernel<<<64, 32>>>(x, trans, out);
}

// round 11
// speedup vs baseline: 1.5528x; 1.5528x over previous
#include <cuda_runtime.h>
#include <cuda_bf16.h>
#include <math.h>
#include <stdint.h>

// Problem constants: B=64, T=512, V=32000, E=256, H=512, 4H=2048, NT=12, C=10
#define NBLK 128          // persistent LSTM blocks (<=148 SMs -> co-resident)
#define PADTAG 0
#define BOS 10
#define EOSx 11

// ---------------- scratch: static device memory (no runtime allocs) ----------
__device__ float    g_X[2][67108864];      // [dir][(b*512+t)*2048 + g*512+u] (NO bias)
__device__ float    g_hid[33554432];       // [((t*64+b)*2 + dir)*512 + u]
__device__ float    g_h[2 * 3 * 512 * 64]; // [dir][buf][k4][b][4] packed carry ring
__device__ float    g_hT[64 * 1024];       // [b][dir*512+u] final carry
__device__ float    g_emis[32768 * 12];    // [(t*64+b)*12 + tag]
__device__ unsigned g_bar;

// ---------------- f32x2 packed-FMA helpers (sm_103a) -------------------------
union U64F2 { unsigned long long u; float2 f2; };
union F4U2  { float4 f4; unsigned long long u2[2]; };

__device__ __forceinline__ unsigned long long fma2(unsigned long long a,
                                                   unsigned long long b,
                                                   unsigned long long c) {
    unsigned long long d;
    asm("fma.rn.f32x2 %0, %1, %2, %3;" : "=l"(d) : "l"(a), "l"(b), "l"(c));
    return d;
}
__device__ __forceinline__ unsigned long long splat2(float a) {
    unsigned long long r;
    asm("mov.b64 %0, {%1, %1};" : "=l"(r) : "f"(a));
    return r;
}
__device__ __forceinline__ void cp_async16(unsigned saddr, const void* gptr) {
    asm volatile("cp.async.cg.shared.global [%0], [%1], 16;"
                 :: "r"(saddr), "l"(gptr));
}

// ---------------- XLA-exact activations --------------------------------------
__device__ __forceinline__ float tanh_xla(float x) {
    const float ax = fabsf(x);
    float xc = fminf(fmaxf(x, -9.0f), 9.0f);
    float x2 = __fmul_rn(xc, xc);
    float p = -2.76076847742355e-16f;
    p = __fadd_rn(__fmul_rn(x2, p),  2.00018790482477e-13f);
    p = __fadd_rn(__fmul_rn(x2, p), -8.60467152213735e-11f);
    p = __fadd_rn(__fmul_rn(x2, p),  5.12229709037114e-08f);
    p = __fadd_rn(__fmul_rn(x2, p),  1.48572235717979e-05f);
    p = __fadd_rn(__fmul_rn(x2, p),  6.37261928875436e-04f);
    p = __fadd_rn(__fmul_rn(x2, p),  4.89352455891786e-03f);
    float num = __fmul_rn(xc, p);
    float q = 1.19825839466702e-06f;
    q = __fadd_rn(__fmul_rn(x2, q), 1.18534705686654e-04f);
    q = __fadd_rn(__fmul_rn(x2, q), 2.26843463243900e-03f);
    q = __fadd_rn(__fmul_rn(x2, q), 4.89352518554385e-03f);
    float r = __fdiv_rn(num, q);
    return (ax < 0.0004f) ? x : r;
}
__device__ __forceinline__ float sigmoid_xla(float x) {
    return __fadd_rn(0.5f, __fmul_rn(0.5f, tanh_xla(__fmul_rn(0.5f, x))));
}

// ---------------- init: reset spin-barrier counter every replay --------------
__global__ void init_kernel() { if (threadIdx.x == 0) g_bar = 0u; }

// ---------------- phase 1: fused embedding gather + input projection GEMM ----
// out[m][n] = emb[x[m]] . W[n][:]  (bias added in lstm). Packed f32x2 over
// output-column pairs: each accumulator's k-chain is bit-identical to scalar.
__global__ __launch_bounds__(256) void gemm_ih(const int* __restrict__ x,
                                               const float* __restrict__ emb,
                                               const float* __restrict__ wf,
                                               const float* __restrict__ wb) {
    __shared__ float As[16][64];
    __shared__ float Bs[16][64];
    __shared__ int   rix[64];
    const int dir = blockIdx.z;
    const float* __restrict__ W = dir ? wb : wf;
    float* __restrict__ Xout = g_X[dir];
    const int tid = threadIdx.x;
    const int m0 = blockIdx.y << 6, n0 = blockIdx.x << 6;

    if (tid < 64) rix[tid] = x[m0 + tid];
    __syncthreads();

    const int r  = tid & 63, kk = tid >> 6;       // loader: row r, k-quad kk
    const int tx = tid & 15, ty = tid >> 4;       // compute: 4x4 micro-tile
    const float* aptr = emb + (size_t)rix[r] * 256 + (kk << 2);
    const float* bptr = W   + (size_t)(n0 + r) * 256 + (kk << 2);

    unsigned long long acc[4][2];
#pragma unroll
    for (int i = 0; i < 4; ++i) { acc[i][0] = 0ull; acc[i][1] = 0ull; }

    for (int kt = 0; kt < 16; ++kt) {
        float4 a = *(const float4*)(aptr + (kt << 4));
        float4 b = *(const float4*)(bptr + (kt << 4));
        __syncthreads();
        As[(kk << 2) + 0][r] = a.x; As[(kk << 2) + 1][r] = a.y;
        As[(kk << 2) + 2][r] = a.z; As[(kk << 2) + 3][r] = a.w;
        Bs[(kk << 2) + 0][r] = b.x; Bs[(kk << 2) + 1][r] = b.y;
        Bs[(kk << 2) + 2][r] = b.z; Bs[(kk << 2) + 3][r] = b.w;
        __syncthreads();
#pragma unroll
        for (int k = 0; k < 16; ++k) {
            float4 av = *(const float4*)&As[k][ty << 2];
            F4U2 bu; bu.f4 = *(const float4*)&Bs[k][tx << 2];
            float ar[4] = {av.x, av.y, av.z, av.w};
#pragma unroll
            for (int i = 0; i < 4; ++i) {
                unsigned long long ai = splat2(ar[i]);
                acc[i][0] = fma2(ai, bu.u2[0], acc[i][0]);
                acc[i][1] = fma2(ai, bu.u2[1], acc[i][1]);
            }
        }
    }
#pragma unroll
    for (int i = 0; i < 4; ++i) {
        size_t m = (size_t)(m0 + (ty << 2) + i);
        U64F2 lo, hi; lo.u = acc[i][0]; hi.u = acc[i][1];
        float4 s = make_float4(lo.f2.x, lo.f2.y, hi.f2.x, hi.f2.y);
        *(float4*)(Xout + m * 2048 + n0 + (tx << 2)) = s;
    }
}

// ---------------- phase 2: persistent bidirectional LSTM ---------------------
// 128 blocks. dir = blk/64; block owns 8 hidden units u0 = (blk%64)*8.
// R9 structure; ONE change: the step's X gate-tile (8KB) is brought into smem
// by cp.async issued at the END of the previous step, so its DRAM latency
// completes inside the grid-barrier wait instead of stalling the epilogue.
#define LSTM_SMEM ((32 * 512 + 512 * 64 + 512 + 64 * 36) * 4)

__device__ __forceinline__ void grid_barrier(unsigned target) {
    __syncthreads();
    if (threadIdx.x == 0) {
        __threadfence();
        atomicAdd(&g_bar, 1u);
        while (*(volatile unsigned*)&g_bar < target) __nanosleep(32);
        __threadfence();
    }
    __syncthreads();
}

__global__ __launch_bounds__(256, 1) void lstm_kernel(const int* __restrict__ x,
                                                      const float* __restrict__ whh_f,
                                                      const float* __restrict__ whh_b,
                                                      const float* __restrict__ bias_f,
                                                      const float* __restrict__ bias_b) {
    extern __shared__ float sm[];
    float* Wsm = sm;                       // 32*512
    float* hsm = sm + 32 * 512;            // packed [k4][b][4] (512*64 floats)
    float* csm = hsm + 512 * 64;           // 8*64   ([j*64+b])
    float* xsm = csm + 512;                // 64*36  ([b][gate*8+j], padded)

    const int tid = threadIdx.x;
    const int blk = blockIdx.x;
    const int dir = blk >> 6;
    const int u0  = (blk & 63) << 3;
    const int b   = tid & 63;
    const int p   = tid >> 6;              // 0..3; thread owns units p, p+4
    const float* __restrict__ Whh = dir ? whh_b : whh_f;
    const float* __restrict__ bia = dir ? bias_b : bias_f;
    const float* __restrict__ Xg  = g_X[dir];
    float* __restrict__ ring = g_h + dir * (3 * 512 * 64);
    const unsigned xsm_base = (unsigned)__cvta_generic_to_shared(xsm);

    // resident weights: local row lr = gate*8 + j  ->  w_hh[gate*512+u0+j][:]
    for (int i = tid; i < 32 * 128; i += 256) {     // float4 granules
        int lr = i >> 7, k4 = (i & 127) << 2;
        int gate = lr >> 3, j = lr & 7;
        float4 v = *(const float4*)&Whh[(size_t)(gate * 512 + u0 + j) * 512 + k4];
        *(float4*)&Wsm[lr * 512 + k4] = v;
    }
    float bb0[4], bb1[4];
#pragma unroll
    for (int g = 0; g < 4; ++g) {
        bb0[g] = bia[g * 512 + u0 + p];
        bb1[g] = bia[g * 512 + u0 + p + 4];
    }
    for (int i = tid; i < 512; i += 256) csm[i] = 0.f;
    // zero ring buffer 0 for own units (packed [k4][b][4] layout)
    for (int i = tid; i < 512; i += 256) {
        int j = i >> 6, bb = i & 63, u = u0 + j;
        ring[((u >> 2) * 64 + bb) * 4 + (u & 3)] = 0.f;
    }
    __threadfence();

    // prefetch X gate-tile for step 0 into xsm (completes during the barrier)
    {
        const int t0 = dir ? 511 : 0;
        int o = tid << 1;
#pragma unroll
        for (int q = 0; q < 2; ++q) {
            int bb2 = o >> 3, g = (o >> 1) & 3, hf = o & 1;
            const float* src = Xg + ((size_t)bb2 * 512 + t0) * 2048
                                  + g * 512 + u0 + hf * 4;
            cp_async16(xsm_base + (unsigned)(bb2 * 36 + g * 8 + hf * 4) * 4, src);
            ++o;
        }
        asm volatile("cp.async.commit_group;" ::: "memory");
    }
    unsigned nbar = 1;
    grid_barrier(nbar * NBLK);

    for (int s = 0; s < 512; ++s) {
        const int t  = dir ? 511 - s : s;
        const int rb = s % 3, wbuf = (s + 1) % 3;

        // X tile for this step is now in flight/complete; make it visible
        asm volatile("cp.async.wait_group 0;" ::: "memory");
        __syncthreads();

        const float4* src4 = (const float4*)(ring + rb * 32768);
        float4* dst4 = (float4*)hsm;
        float4 rreg[8];
#pragma unroll
        for (int q = 0; q < 8; ++q) rreg[q] = __ldcg(src4 + tid + 256 * q);

        unsigned long long d0[4] = {0ull, 0ull, 0ull, 0ull};
        unsigned long long d1[4] = {0ull, 0ull, 0ull, 0ull};

        for (int c = 0; c < 4; ++c) {
#pragma unroll
            for (int q = 0; q < 8; ++q)
                dst4[c * 2048 + tid + 256 * q] = rreg[q];
            if (c < 3) {
#pragma unroll
                for (int q = 0; q < 8; ++q)
                    rreg[q] = __ldcg(src4 + (c + 1) * 2048 + tid + 256 * q);
            }
            __syncthreads();
            const int kbeg = c << 7;
#pragma unroll 4
            for (int k = kbeg; k < kbeg + 128; k += 4) {
                F4U2 h4; h4.f4 = *(const float4*)&hsm[((k >> 2) * 64 + b) * 4];
#pragma unroll
                for (int g = 0; g < 4; ++g) {
                    F4U2 w0; w0.f4 = *(const float4*)&Wsm[(g * 8 + p) * 512 + k];
                    d0[g] = fma2(h4.u2[0], w0.u2[0], d0[g]);
                    d0[g] = fma2(h4.u2[1], w0.u2[1], d0[g]);
                    F4U2 w1; w1.f4 = *(const float4*)&Wsm[(g * 8 + p + 4) * 512 + k];
                    d1[g] = fma2(h4.u2[0], w1.u2[0], d1[g]);
                    d1[g] = fma2(h4.u2[1], w1.u2[1], d1[g]);
                }
            }
        }

        const bool mk = (x[b * 512 + t] != 0);
#pragma unroll
        for (int half = 0; half < 2; ++half) {
            const unsigned long long* dd = half ? d1 : d0;
            const float* bv = half ? bb1 : bb0;
            const int j = p + half * 4;
            const int u = u0 + j;
            U64F2 e0, e1, e2, e3;
            e0.u = dd[0]; e1.u = dd[1]; e2.u = dd[2]; e3.u = dd[3];
            float s0 = __fadd_rn(e0.f2.x, e0.f2.y);
            float s1 = __fadd_rn(e1.f2.x, e1.f2.y);
            float s2 = __fadd_rn(e2.f2.x, e2.f2.y);
            float s3 = __fadd_rn(e3.f2.x, e3.f2.y);
            // X gate values come from the prefetched smem tile
            float zi = __fadd_rn(__fadd_rn(xsm[b * 36 + 0 * 8 + j], s0), bv[0]);
            float zf = __fadd_rn(__fadd_rn(xsm[b * 36 + 1 * 8 + j], s1), bv[1]);
            float zg = __fadd_rn(__fadd_rn(xsm[b * 36 + 2 * 8 + j], s2), bv[2]);
            float zo = __fadd_rn(__fadd_rn(xsm[b * 36 + 3 * 8 + j], s3), bv[3]);
            float ii = sigmoid_xla(zi);
            float ff = sigmoid_xla(zf);
            float oo = sigmoid_xla(zo);
            float gg = tanh_xla(zg);
            float cold = csm[j * 64 + b];
            float cn = __fadd_rn(__fmul_rn(ff, cold), __fmul_rn(ii, gg));
            float hn = __fmul_rn(oo, tanh_xla(cn));
            float hold = hsm[((u >> 2) * 64 + b) * 4 + (u & 3)];
            float ck = mk ? cn : cold;
            float hk = mk ? hn : hold;
            csm[j * 64 + b] = ck;
            g_hid[((size_t)(t * 64 + b) * 2 + dir) * 512 + u] = mk ? hn : 0.f;
            ring[wbuf * 32768 + ((u >> 2) * 64 + b) * 4 + (u & 3)] = hk;
            if (s == 511) g_hT[b * 1024 + dir * 512 + u] = hk;
        }
        // all threads done reading xsm before the next prefetch overwrites it
        __syncthreads();
        if (s < 511) {
            const int tn = dir ? 510 - s : s + 1;
            int o = tid << 1;
#pragma unroll
            for (int q = 0; q < 2; ++q) {
                int bb2 = o >> 3, g = (o >> 1) & 3, hf = o & 1;
                const float* src = Xg + ((size_t)bb2 * 512 + tn) * 2048
                                      + g * 512 + u0 + hf * 4;
                cp_async16(xsm_base + (unsigned)(bb2 * 36 + g * 8 + hf * 4) * 4, src);
                ++o;
            }
            asm volatile("cp.async.commit_group;" ::: "memory");
        }
        __threadfence();
        ++nbar;
        grid_barrier(nbar * NBLK);
    }
}

// ---------------- phase 3: emissions = hid @ fc_w.T + fc_b -------------------
// fp32 Kahan + exact product tail (fmaf residual); fp64 only for the 32-lane
// reduction. Error ~1e-13 — no DFMA-pipe cost.
__global__ __launch_bounds__(256) void emis_kernel(const float* __restrict__ fcw,
                                                   const float* __restrict__ fcb) {
    const int warp = (blockIdx.x * 256 + threadIdx.x) >> 5;
    const int lane = threadIdx.x & 31;
    if (warp >= 32768) return;
    const float* hrow = g_hid + (size_t)warp * 1024;
    float s[12], c[12], ec[12];
#pragma unroll
    for (int j = 0; j < 12; ++j) { s[j] = 0.f; c[j] = 0.f; ec[j] = 0.f; }
    for (int k = lane; k < 1024; k += 32) {
        float hv = hrow[k];
#pragma unroll
        for (int j = 0; j < 12; ++j) {
            float w = __ldg(&fcw[j * 1024 + k]);
            float p = __fmul_rn(hv, w);
            float e = __fmaf_rn(hv, w, -p);          // exact product tail
            ec[j] = __fadd_rn(ec[j], e);
            float y = __fsub_rn(p, c[j]);            // Kahan
            float t = __fadd_rn(s[j], y);
            c[j] = __fsub_rn(__fsub_rn(t, s[j]), y);
            s[j] = t;
        }
    }
#pragma unroll
    for (int j = 0; j < 12; ++j) {
        double acc = (double)s[j] - (double)c[j] + (double)ec[j];
#pragma unroll
        for (int off = 16; off; off >>= 1)
            acc += __shfl_down_sync(0xffffffffu, acc, off);
        if (lane == 0)
            g_emis[(size_t)warp * 12 + j] = __fadd_rn((float)acc, fcb[j]);
    }
}

// ---------------- phase 4: class probs = softmax(hT @ fc2_w.T + fc2_b) -------
__global__ __launch_bounds__(32) void cls_kernel(const float* __restrict__ w2,
                                                 const float* __restrict__ b2,
                                                 float* __restrict__ out) {
    const int bb = blockIdx.x;
    const int lane = threadIdx.x;
    double acc[10];
#pragma unroll
    for (int j = 0; j < 10; ++j) acc[j] = 0.0;
    for (int k = lane; k < 1024; k += 32) {
        double hv = (double)g_hT[bb * 1024 + k];
#pragma unroll
        for (int j = 0; j < 10; ++j)
            acc[j] = fma(hv, (double)__ldg(&w2[j * 1024 + k]), acc[j]);
    }
#pragma unroll
    for (int j = 0; j < 10; ++j)
#pragma unroll
        for (int off = 16; off; off >>= 1)
            acc[j] += __shfl_down_sync(0xffffffffu, acc[j], off);
    if (lane == 0) {
        float z[10], mx = -1e30f, ssum = 0.f;
#pragma unroll
        for (int j = 0; j < 10; ++j) { z[j] = __fadd_rn((float)acc[j], b2[j]); mx = fmaxf(mx, z[j]); }
#pragma unroll
        for (int j = 0; j < 10; ++j) { z[j] = expf(z[j] - mx); ssum += z[j]; }
        float inv = 1.f / ssum;
#pragma unroll
        for (int j = 0; j < 10; ++j) out[64 + 32768 + bb * 10 + j] = z[j] * inv;
    }
}

// ---------------- phase 5: Viterbi — warp-synchronous, shfl-based ------------
__global__ __launch_bounds__(32) void vit_kernel(const int* __restrict__ x,
                                                 const float* __restrict__ trans,
                                                 float* __restrict__ out) {
    const int bb = blockIdx.x;
    const int lane = threadIdx.x;
    __shared__ float tr[144];
    __shared__ short bp[511][12];
    __shared__ short path[512];

    for (int i = lane; i < 144; i += 32) tr[i] = trans[i];
    __syncwarp();

    float tcol[12];
#pragma unroll
    for (int i = 0; i < 12; ++i) tcol[i] = (lane < 12) ? tr[i * 12 + lane] : 0.f;

    float alph = (lane < 12)
        ? __fadd_rn(tr[BOS * 12 + lane], g_emis[(size_t)(0 * 64 + bb) * 12 + lane])
        : -1e30f;

    float e_cur = (lane < 12) ? g_emis[(size_t)(1 * 64 + bb) * 12 + lane] : 0.f;
    int   v_cur = (x[bb * 512 + 1] != 0);

    for (int t = 1; t < 512; ++t) {
        float e_nxt = 0.f; int v_nxt = 0;
        if (t < 511) {
            e_nxt = (lane < 12) ? g_emis[(size_t)((t + 1) * 64 + bb) * 12 + lane] : 0.f;
            v_nxt = (x[bb * 512 + t + 1] != 0);
        }
        float best = -1e30f; int bi = 0;
#pragma unroll
        for (int i = 0; i < 12; ++i) {
            float ai = __shfl_sync(0xffffffffu, alph, i);
            float sc = __fadd_rn(ai, tcol[i]);
            if (sc > best) { best = sc; bi = i; }    // first-index tie-break
        }
        if (lane < 12) {
            alph = v_cur ? __fadd_rn(best, e_cur) : alph;
            bp[t - 1][lane] = v_cur ? (short)bi : (short)lane;
        }
        e_cur = e_nxt; v_cur = v_nxt;
    }
    __syncwarp();

    float fin = -1e30f;
    if (lane < 12) fin = __fadd_rn(alph, tr[lane * 12 + EOSx]);
    float best = -1e30f; int bt = 0;
#pragma unroll
    for (int i = 0; i < 12; ++i) {
        float fi = __shfl_sync(0xffffffffu, fin, i);
        if (fi > best) { best = fi; bt = i; }
    }
    if (lane == 0) {
        out[bb] = best;
        int tag = bt;
        for (int t = 511; t >= 1; --t) { path[t] = (short)tag; tag = bp[t - 1][tag]; }
        path[0] = (short)tag;
    }
    __syncwarp();
    for (int t = lane; t < 512; t += 32)
        out[64 + bb * 512 + t] = (x[bb * 512 + t] != 0) ? (float)path[t] : (float)PADTAG;
}

// ---------------- launcher ---------------------------------------------------
extern "C" void kernel_launch(void* const* d_in, const int* in_sizes, int n_in,
                              void* d_out, int out_size) {
    const int*   x      = (const int*)d_in[0];
    const float* emb    = (const float*)d_in[1];
    const float* w_ih_f = (const float*)d_in[2];
    const float* w_hh_f = (const float*)d_in[3];
    const float* b_f    = (const float*)d_in[4];
    const float* w_ih_b = (const float*)d_in[5];
    const float* w_hh_b = (const float*)d_in[6];
    const float* b_b    = (const float*)d_in[7];
    const float* fc_w   = (const float*)d_in[8];
    const float* fc_b   = (const float*)d_in[9];
    const float* fc2_w  = (const float*)d_in[10];
    const float* fc2_b  = (const float*)d_in[11];
    const float* trans  = (const float*)d_in[12];
    float* out = (float*)d_out;

    cudaFuncSetAttribute(lstm_kernel,
                         cudaFuncAttributeMaxDynamicSharedMemorySize, LSTM_SMEM);

    init_kernel<<<1, 32>>>();
    gemm_ih<<<dim3(32, 512, 2), 256>>>(x, emb, w_ih_f, w_ih_b);
    lstm_kernel<<<NBLK, 256, LSTM_SMEM>>>(x, w_hh_f, w_hh_b, b_f, b_b);
    emis_kernel<<<4096, 256>>>(fc_w, fc_b);
    cls_kernel<<<64, 32>>>(fc2_w, fc2_b, out);
    vit_kernel<<<64, 32>>>(x, trans, out);
}

// round 15
// speedup vs baseline: 1.6100x; 1.0368x over previous
#include <cuda_runtime.h>
#include <cuda_bf16.h>
#include <math.h>
#include <stdint.h>

// Problem constants: B=64, T=512, V=32000, E=256, H=512, 4H=2048, NT=12, C=10
#define NBLK 128          // persistent LSTM blocks (<=148 SMs -> co-resident)
#define PADTAG 0
#define BOS 10
#define EOSx 11

// ---------------- scratch: static device memory (no runtime allocs) ----------
__device__ float    g_X[2][67108864];      // [dir][(b*512+t)*2048 + g*512+u] (NO bias)
__device__ float    g_hid[33554432];       // [(dir*512+u)][t*64+b]  (coalesced)
__device__ float    g_h[2 * 3 * 512 * 64]; // [dir][buf][k4][b][4] packed carry ring
__device__ float    g_hT[64 * 1024];       // [b][dir*512+u] final carry
__device__ float    g_emis[32768 * 12];    // [(t*64+b)*12 + tag]
__device__ unsigned g_bar;

// ---------------- f32x2 packed-FMA helpers (sm_103a) -------------------------
union U64F2 { unsigned long long u; float2 f2; };
union F4U2  { float4 f4; unsigned long long u2[2]; };

__device__ __forceinline__ unsigned long long fma2(unsigned long long a,
                                                   unsigned long long b,
                                                   unsigned long long c) {
    unsigned long long d;
    asm("fma.rn.f32x2 %0, %1, %2, %3;" : "=l"(d) : "l"(a), "l"(b), "l"(c));
    return d;
}
__device__ __forceinline__ unsigned long long splat2(float a) {
    unsigned long long r;
    asm("mov.b64 %0, {%1, %1};" : "=l"(r) : "f"(a));
    return r;
}
__device__ __forceinline__ void cp_async16(unsigned saddr, const void* gptr) {
    asm volatile("cp.async.cg.shared.global [%0], [%1], 16;"
                 :: "r"(saddr), "l"(gptr));
}

// ---------------- XLA-exact activations --------------------------------------
__device__ __forceinline__ float tanh_xla(float x) {
    const float ax = fabsf(x);
    float xc = fminf(fmaxf(x, -9.0f), 9.0f);
    float x2 = __fmul_rn(xc, xc);
    float p = -2.76076847742355e-16f;
    p = __fadd_rn(__fmul_rn(x2, p),  2.00018790482477e-13f);
    p = __fadd_rn(__fmul_rn(x2, p), -8.60467152213735e-11f);
    p = __fadd_rn(__fmul_rn(x2, p),  5.12229709037114e-08f);
    p = __fadd_rn(__fmul_rn(x2, p),  1.48572235717979e-05f);
    p = __fadd_rn(__fmul_rn(x2, p),  6.37261928875436e-04f);
    p = __fadd_rn(__fmul_rn(x2, p),  4.89352455891786e-03f);
    float num = __fmul_rn(xc, p);
    float q = 1.19825839466702e-06f;
    q = __fadd_rn(__fmul_rn(x2, q), 1.18534705686654e-04f);
    q = __fadd_rn(__fmul_rn(x2, q), 2.26843463243900e-03f);
    q = __fadd_rn(__fmul_rn(x2, q), 4.89352518554385e-03f);
    float r = __fdiv_rn(num, q);
    return (ax < 0.0004f) ? x : r;
}
__device__ __forceinline__ float sigmoid_xla(float x) {
    return __fadd_rn(0.5f, __fmul_rn(0.5f, tanh_xla(__fmul_rn(0.5f, x))));
}

// ---------------- init: reset spin-barrier counter every replay --------------
__global__ void init_kernel() { if (threadIdx.x == 0) g_bar = 0u; }

// ---------------- phase 1: fused embedding gather + input projection GEMM ----
// out[m][n] = emb[x[m]] . W[n][:]  (bias added in lstm). Packed f32x2 over
// output-column pairs: each accumulator's k-chain is bit-identical to scalar.
__global__ __launch_bounds__(256) void gemm_ih(const int* __restrict__ x,
                                               const float* __restrict__ emb,
                                               const float* __restrict__ wf,
                                               const float* __restrict__ wb) {
    __shared__ float As[16][64];
    __shared__ float Bs[16][64];
    __shared__ int   rix[64];
    const int dir = blockIdx.z;
    const float* __restrict__ W = dir ? wb : wf;
    float* __restrict__ Xout = g_X[dir];
    const int tid = threadIdx.x;
    const int m0 = blockIdx.y << 6, n0 = blockIdx.x << 6;

    if (tid < 64) rix[tid] = x[m0 + tid];
    __syncthreads();

    const int r  = tid & 63, kk = tid >> 6;       // loader: row r, k-quad kk
    const int tx = tid & 15, ty = tid >> 4;       // compute: 4x4 micro-tile
    const float* aptr = emb + (size_t)rix[r] * 256 + (kk << 2);
    const float* bptr = W   + (size_t)(n0 + r) * 256 + (kk << 2);

    unsigned long long acc[4][2];
#pragma unroll
    for (int i = 0; i < 4; ++i) { acc[i][0] = 0ull; acc[i][1] = 0ull; }

    for (int kt = 0; kt < 16; ++kt) {
        float4 a = *(const float4*)(aptr + (kt << 4));
        float4 b = *(const float4*)(bptr + (kt << 4));
        __syncthreads();
        As[(kk << 2) + 0][r] = a.x; As[(kk << 2) + 1][r] = a.y;
        As[(kk << 2) + 2][r] = a.z; As[(kk << 2) + 3][r] = a.w;
        Bs[(kk << 2) + 0][r] = b.x; Bs[(kk << 2) + 1][r] = b.y;
        Bs[(kk << 2) + 2][r] = b.z; Bs[(kk << 2) + 3][r] = b.w;
        __syncthreads();
#pragma unroll
        for (int k = 0; k < 16; ++k) {
            float4 av = *(const float4*)&As[k][ty << 2];
            F4U2 bu; bu.f4 = *(const float4*)&Bs[k][tx << 2];
            float ar[4] = {av.x, av.y, av.z, av.w};
#pragma unroll
            for (int i = 0; i < 4; ++i) {
                unsigned long long ai = splat2(ar[i]);
                acc[i][0] = fma2(ai, bu.u2[0], acc[i][0]);
                acc[i][1] = fma2(ai, bu.u2[1], acc[i][1]);
            }
        }
    }
#pragma unroll
    for (int i = 0; i < 4; ++i) {
        size_t m = (size_t)(m0 + (ty << 2) + i);
        U64F2 lo, hi; lo.u = acc[i][0]; hi.u = acc[i][1];
        float4 s = make_float4(lo.f2.x, lo.f2.y, hi.f2.x, hi.f2.y);
        *(float4*)(Xout + m * 2048 + n0 + (tx << 2)) = s;
    }
}

// ---------------- phase 2: persistent bidirectional LSTM ---------------------
// 128 blocks. dir = blk/64; block owns 8 hidden units u0 = (blk%64)*8.
// R11 structure; this round removes per-step fence/drain costs:
//   - g_hid stores coalesced ([u][t*64+b])
//   - ring stores bounced through smem -> one coalesced STG.128 sweep
//   - release/acquire grid barrier (no full __threadfence)
//   - pad mask precomputed once into a smem bitmask
// Smem floats: Wsm 16384 | hsm 32768 | csm 512 | xsm 2304 | hnew 512 | msk 1024
#define LSTM_SMEM ((16384 + 32768 + 512 + 2304 + 512 + 1024) * 4)

__device__ __forceinline__ void grid_barrier(unsigned target) {
    __syncthreads();
    if (threadIdx.x == 0) {
        asm volatile("red.release.gpu.global.add.u32 [%0], %1;"
                     :: "l"(&g_bar), "r"(1u) : "memory");
        unsigned v;
        while (1) {
            asm volatile("ld.acquire.gpu.global.u32 %0, [%1];"
                         : "=r"(v) : "l"(&g_bar) : "memory");
            if (v >= target) break;
            __nanosleep(32);
        }
    }
    __syncthreads();
}

__global__ __launch_bounds__(256, 1) void lstm_kernel(const int* __restrict__ x,
                                                      const float* __restrict__ whh_f,
                                                      const float* __restrict__ whh_b,
                                                      const float* __restrict__ bias_f,
                                                      const float* __restrict__ bias_b) {
    extern __shared__ float sm[];
    float* Wsm  = sm;                      // 32*512
    float* hsm  = Wsm + 16384;             // packed [k4][b][4] (512*64 floats)
    float* csm  = hsm + 32768;             // 8*64   ([j*64+b])
    float* xsm  = csm + 512;               // 64*36  ([b][gate*8+j], padded)
    float* hnew = xsm + 2304;              // 8*64   ([j*64+b]) new carry bounce
    unsigned* msk = (unsigned*)(hnew + 512); // 64*16 bitmask words [b][t/32]

    const int tid = threadIdx.x;
    const int blk = blockIdx.x;
    const int dir = blk >> 6;
    const int u0  = (blk & 63) << 3;
    const int b   = tid & 63;
    const int p   = tid >> 6;              // 0..3; thread owns units p, p+4
    const float* __restrict__ Whh = dir ? whh_b : whh_f;
    const float* __restrict__ bia = dir ? bias_b : bias_f;
    const float* __restrict__ Xg  = g_X[dir];
    float* __restrict__ ring = g_h + dir * (3 * 512 * 64);
    const unsigned xsm_base = (unsigned)__cvta_generic_to_shared(xsm);

    // resident weights: local row lr = gate*8 + j  ->  w_hh[gate*512+u0+j][:]
    for (int i = tid; i < 32 * 128; i += 256) {     // float4 granules
        int lr = i >> 7, k4 = (i & 127) << 2;
        int gate = lr >> 3, j = lr & 7;
        float4 v = *(const float4*)&Whh[(size_t)(gate * 512 + u0 + j) * 512 + k4];
        *(float4*)&Wsm[lr * 512 + k4] = v;
    }
    float bb0[4], bb1[4];
#pragma unroll
    for (int g = 0; g < 4; ++g) {
        bb0[g] = bia[g * 512 + u0 + p];
        bb1[g] = bia[g * 512 + u0 + p + 4];
    }
    for (int i = tid; i < 512; i += 256) csm[i] = 0.f;
    // pad-mask bitmap: msk[b*16 + w] bit i = (x[b][w*32+i] != 0)
    for (int i = tid; i < 1024; i += 256) {
        int bb2 = i >> 4, w = i & 15;
        unsigned m = 0;
        for (int bit = 0; bit < 32; ++bit)
            m |= (x[bb2 * 512 + w * 32 + bit] != 0) ? (1u << bit) : 0u;
        msk[i] = m;
    }
    // zero ring buffer 0 for own units (packed [k4][b][4] layout)
    for (int i = tid; i < 512; i += 256) {
        int j = i >> 6, bb = i & 63, u = u0 + j;
        ring[((u >> 2) * 64 + bb) * 4 + (u & 3)] = 0.f;
    }

    // prefetch X gate-tile for step 0 into xsm (completes during the barrier)
    {
        const int t0 = dir ? 511 : 0;
        int o = tid << 1;
#pragma unroll
        for (int q = 0; q < 2; ++q) {
            int bb2 = o >> 3, g = (o >> 1) & 3, hf = o & 1;
            const float* src = Xg + ((size_t)bb2 * 512 + t0) * 2048
                                  + g * 512 + u0 + hf * 4;
            cp_async16(xsm_base + (unsigned)(bb2 * 36 + g * 8 + hf * 4) * 4, src);
            ++o;
        }
        asm volatile("cp.async.commit_group;" ::: "memory");
    }
    unsigned nbar = 1;
    grid_barrier(nbar * NBLK);   // release publishes ring zeroing

    for (int s = 0; s < 512; ++s) {
        const int t  = dir ? 511 - s : s;
        const int rb = s % 3, wbuf = (s + 1) % 3;

        // X tile for this step is now in flight/complete; make it visible
        asm volatile("cp.async.wait_group 0;" ::: "memory");
        __syncthreads();

        const float4* src4 = (const float4*)(ring + rb * 32768);
        float4* dst4 = (float4*)hsm;
        float4 rreg[8];
#pragma unroll
        for (int q = 0; q < 8; ++q) rreg[q] = __ldcg(src4 + tid + 256 * q);

        unsigned long long d0[4] = {0ull, 0ull, 0ull, 0ull};
        unsigned long long d1[4] = {0ull, 0ull, 0ull, 0ull};

        for (int c = 0; c < 4; ++c) {
#pragma unroll
            for (int q = 0; q < 8; ++q)
                dst4[c * 2048 + tid + 256 * q] = rreg[q];
            if (c < 3) {
#pragma unroll
                for (int q = 0; q < 8; ++q)
                    rreg[q] = __ldcg(src4 + (c + 1) * 2048 + tid + 256 * q);
            }
            __syncthreads();
            const int kbeg = c << 7;
#pragma unroll 4
            for (int k = kbeg; k < kbeg + 128; k += 4) {
                F4U2 h4; h4.f4 = *(const float4*)&hsm[((k >> 2) * 64 + b) * 4];
#pragma unroll
                for (int g = 0; g < 4; ++g) {
                    F4U2 w0; w0.f4 = *(const float4*)&Wsm[(g * 8 + p) * 512 + k];
                    d0[g] = fma2(h4.u2[0], w0.u2[0], d0[g]);
                    d0[g] = fma2(h4.u2[1], w0.u2[1], d0[g]);
                    F4U2 w1; w1.f4 = *(const float4*)&Wsm[(g * 8 + p + 4) * 512 + k];
                    d1[g] = fma2(h4.u2[0], w1.u2[0], d1[g]);
                    d1[g] = fma2(h4.u2[1], w1.u2[1], d1[g]);
                }
            }
        }

        const bool mk = (msk[b * 16 + (t >> 5)] >> (t & 31)) & 1u;
#pragma unroll
        for (int half = 0; half < 2; ++half) {
            const unsigned long long* dd = half ? d1 : d0;
            const float* bv = half ? bb1 : bb0;
            const int j = p + half * 4;
            const int u = u0 + j;
            U64F2 e0, e1, e2, e3;
            e0.u = dd[0]; e1.u = dd[1]; e2.u = dd[2]; e3.u = dd[3];
            float s0 = __fadd_rn(e0.f2.x, e0.f2.y);
            float s1 = __fadd_rn(e1.f2.x, e1.f2.y);
            float s2 = __fadd_rn(e2.f2.x, e2.f2.y);
            float s3 = __fadd_rn(e3.f2.x, e3.f2.y);
            // X gate values come from the prefetched smem tile
            float zi = __fadd_rn(__fadd_rn(xsm[b * 36 + 0 * 8 + j], s0), bv[0]);
            float zf = __fadd_rn(__fadd_rn(xsm[b * 36 + 1 * 8 + j], s1), bv[1]);
            float zg = __fadd_rn(__fadd_rn(xsm[b * 36 + 2 * 8 + j], s2), bv[2]);
            float zo = __fadd_rn(__fadd_rn(xsm[b * 36 + 3 * 8 + j], s3), bv[3]);
            float ii = sigmoid_xla(zi);
            float ff = sigmoid_xla(zf);
            float oo = sigmoid_xla(zo);
            float gg = tanh_xla(zg);
            float cold = csm[j * 64 + b];
            float cn = __fadd_rn(__fmul_rn(ff, cold), __fmul_rn(ii, gg));
            float hn = __fmul_rn(oo, tanh_xla(cn));
            float hold = hsm[((u >> 2) * 64 + b) * 4 + (u & 3)];
            float ck = mk ? cn : cold;
            float hk = mk ? hn : hold;
            csm[j * 64 + b] = ck;
            // coalesced store: [dir*512+u][t*64+b]
            g_hid[(size_t)(dir * 512 + u) * 32768 + t * 64 + b] = mk ? hn : 0.f;
            hnew[j * 64 + b] = hk;                 // smem bounce for ring
            if (s == 511) g_hT[b * 1024 + dir * 512 + u] = hk;
        }
        // hnew complete + xsm free for next prefetch
        __syncthreads();
        // coalesced ring write: 128 threads sweep the block's 2KB carry slice
        if (tid < 128) {
            const int q = tid >> 6, bb2 = tid & 63;
            float4 v;
            v.x = hnew[(q * 4 + 0) * 64 + bb2];
            v.y = hnew[(q * 4 + 1) * 64 + bb2];
            v.z = hnew[(q * 4 + 2) * 64 + bb2];
            v.w = hnew[(q * 4 + 3) * 64 + bb2];
            *(float4*)&ring[wbuf * 32768 + (u0 >> 2) * 256 + tid * 4] = v;
        }
        if (s < 511) {
            const int tn = dir ? 510 - s : s + 1;
            int o = tid << 1;
#pragma unroll
            for (int q = 0; q < 2; ++q) {
                int bb2 = o >> 3, g = (o >> 1) & 3, hf = o & 1;
                const float* src = Xg + ((size_t)bb2 * 512 + tn) * 2048
                                      + g * 512 + u0 + hf * 4;
                cp_async16(xsm_base + (unsigned)(bb2 * 36 + g * 8 + hf * 4) * 4, src);
                ++o;
            }
            asm volatile("cp.async.commit_group;" ::: "memory");
        }
        ++nbar;
        grid_barrier(nbar * NBLK);   // release orders ring/g_hid stores
    }
}

// ---------------- phase 3: emissions = hid @ fc_w.T + fc_b -------------------
// Thread per (t,b); hid reads coalesced from [u][t*64+b]; fc_w in smem.
// FMA-Kahan (validated in R10): compensation also captures product rounding.
__global__ __launch_bounds__(256) void emis_kernel(const float* __restrict__ fcw,
                                                   const float* __restrict__ fcb) {
    __shared__ float smw[12 * 1024];
    const int tid = threadIdx.x;
    const int tb  = blockIdx.x * 256 + tid;
    for (int i = tid; i < 12288; i += 256) smw[i] = fcw[i];
    __syncthreads();
    float s[12], c[12];
#pragma unroll
    for (int j = 0; j < 12; ++j) { s[j] = 0.f; c[j] = 0.f; }
#pragma unroll 2
    for (int k = 0; k < 1024; ++k) {
        float hv = __ldcs(&g_hid[(size_t)k * 32768 + tb]);
#pragma unroll
        for (int j = 0; j < 12; ++j) {
            float y = __fmaf_rn(hv, smw[j * 1024 + k], -c[j]);
            float t = __fadd_rn(s[j], y);
            c[j] = __fsub_rn(__fsub_rn(t, s[j]), y);
            s[j] = t;
        }
    }
#pragma unroll
    for (int j = 0; j < 12; ++j) {
        float r = (float)((double)s[j] - (double)c[j]);
        g_emis[(size_t)tb * 12 + j] = __fadd_rn(r, fcb[j]);
    }
}

// ---------------- phase 4: class probs = softmax(hT @ fc2_w.T + fc2_b) -------
__global__ __launch_bounds__(32) void cls_kernel(const float* __restrict__ w2,
                                                 const float* __restrict__ b2,
                                                 float* __restrict__ out) {
    const int bb = blockIdx.x;
    const int lane = threadIdx.x;
    double acc[10];
#pragma unroll
    for (int j = 0; j < 10; ++j) acc[j] = 0.0;
    for (int k = lane; k < 1024; k += 32) {
        double hv = (double)g_hT[bb * 1024 + k];
#pragma unroll
        for (int j = 0; j < 10; ++j)
            acc[j] = fma(hv, (double)__ldg(&w2[j * 1024 + k]), acc[j]);
    }
#pragma unroll
    for (int j = 0; j < 10; ++j)
#pragma unroll
        for (int off = 16; off; off >>= 1)
            acc[j] += __shfl_down_sync(0xffffffffu, acc[j], off);
    if (lane == 0) {
        float z[10], mx = -1e30f, ssum = 0.f;
#pragma unroll
        for (int j = 0; j < 10; ++j) { z[j] = __fadd_rn((float)acc[j], b2[j]); mx = fmaxf(mx, z[j]); }
#pragma unroll
        for (int j = 0; j < 10; ++j) { z[j] = expf(z[j] - mx); ssum += z[j]; }
        float inv = 1.f / ssum;
#pragma unroll
        for (int j = 0; j < 10; ++j) out[64 + 32768 + bb * 10 + j] = z[j] * inv;
    }
}

// ---------------- phase 5: Viterbi — warp-synchronous, shfl-based ------------
__global__ __launch_bounds__(32) void vit_kernel(const int* __restrict__ x,
                                                 const float* __restrict__ trans,
                                                 float* __restrict__ out) {
    const int bb = blockIdx.x;
    const int lane = threadIdx.x;
    __shared__ float tr[144];
    __shared__ short bp[511][12];
    __shared__ short path[512];

    for (int i = lane; i < 144; i += 32) tr[i] = trans[i];
    __syncwarp();

    float tcol[12];
#pragma unroll
    for (int i = 0; i < 12; ++i) tcol[i] = (lane < 12) ? tr[i * 12 + lane] : 0.f;

    float alph = (lane < 12)
        ? __fadd_rn(tr[BOS * 12 + lane], g_emis[(size_t)(0 * 64 + bb) * 12 + lane])
        : -1e30f;

    float e_cur = (lane < 12) ? g_emis[(size_t)(1 * 64 + bb) * 12 + lane] : 0.f;
    int   v_cur = (x[bb * 512 + 1] != 0);

    for (int t = 1; t < 512; ++t) {
        float e_nxt = 0.f; int v_nxt = 0;
        if (t < 511) {
            e_nxt = (lane < 12) ? g_emis[(size_t)((t + 1) * 64 + bb) * 12 + lane] : 0.f;
            v_nxt = (x[bb * 512 + t + 1] != 0);
        }
        float best = -1e30f; int bi = 0;
#pragma unroll
        for (int i = 0; i < 12; ++i) {
            float ai = __shfl_sync(0xffffffffu, alph, i);
            float sc = __fadd_rn(ai, tcol[i]);
            if (sc > best) { best = sc; bi = i; }    // first-index tie-break
        }
        if (lane < 12) {
            alph = v_cur ? __fadd_rn(best, e_cur) : alph;
            bp[t - 1][lane] = v_cur ? (short)bi : (short)lane;
        }
        e_cur = e_nxt; v_cur = v_nxt;
    }
    __syncwarp();

    float fin = -1e30f;
    if (lane < 12) fin = __fadd_rn(alph, tr[lane * 12 + EOSx]);
    float best = -1e30f; int bt = 0;
#pragma unroll
    for (int i = 0; i < 12; ++i) {
        float fi = __shfl_sync(0xffffffffu, fin, i);
        if (fi > best) { best = fi; bt = i; }
    }
    if (lane == 0) {
        out[bb] = best;
        int tag = bt;
        for (int t = 511; t >= 1; --t) { path[t] = (short)tag; tag = bp[t - 1][tag]; }
        path[0] = (short)tag;
    }
    __syncwarp();
    for (int t = lane; t < 512; t += 32)
        out[64 + bb * 512 + t] = (x[bb * 512 + t] != 0) ? (float)path[t] : (float)PADTAG;
}

// ---------------- launcher ---------------------------------------------------
extern "C" void kernel_launch(void* const* d_in, const int* in_sizes, int n_in,
                              void* d_out, int out_size) {
    const int*   x      = (const int*)d_in[0];
    const float* emb    = (const float*)d_in[1];
    const float* w_ih_f = (const float*)d_in[2];
    const float* w_hh_f = (const float*)d_in[3];
    const float* b_f    = (const float*)d_in[4];
    const float* w_ih_b = (const float*)d_in[5];
    const float* w_hh_b = (const float*)d_in[6];
    const float* b_b    = (const float*)d_in[7];
    const float* fc_w   = (const float*)d_in[8];
    const float* fc_b   = (const float*)d_in[9];
    const float* fc2_w  = (const float*)d_in[10];
    const float* fc2_b  = (const float*)d_in[11];
    const float* trans  = (const float*)d_in[12];
    float* out = (float*)d_out;

    cudaFuncSetAttribute(lstm_kernel,
                         cudaFuncAttributeMaxDynamicSharedMemorySize, LSTM_SMEM);

    init_kernel<<<1, 32>>>();
    gemm_ih<<<dim3(32, 512, 2), 256>>>(x, emb, w_ih_f, w_ih_b);
    lstm_kernel<<<NBLK, 256, LSTM_SMEM>>>(x, w_hh_f, w_hh_b, b_f, b_b);
    emis_kernel<<<128, 256>>>(fc_w, fc_b);
    cls_kernel<<<64, 32>>>(fc2_w, fc2_b, out);
    vit_kernel<<<64, 32>>>(x, trans, out);
}

// round 17
// speedup vs baseline: 1.6460x; 1.0224x over previous
#include <cuda_runtime.h>
#include <cuda_bf16.h>
#include <math.h>
#include <stdint.h>

// Problem constants: B=64, T=512, V=32000, E=256, H=512, 4H=2048, NT=12, C=10
#define NBLK 128          // persistent LSTM blocks (<=148 SMs -> co-resident)
#define PADTAG 0
#define BOS 10
#define EOSx 11

// ---------------- scratch: static device memory (no runtime allocs) ----------
__device__ float    g_X[2][67108864];      // [dir][(b*512+t)*2048 + g*512+u] (NO bias)
__device__ float    g_hid[33554432];       // [(dir*512+u)][t*64+b]  (coalesced)
__device__ float    g_h[2 * 3 * 512 * 64]; // [dir][buf][k4][b][4] packed carry ring
__device__ float    g_hT[64 * 1024];       // [b][dir*512+u] final carry
__device__ float    g_emis[32768 * 12];    // [(t*64+b)*12 + tag]
__device__ unsigned g_bar;

// ---------------- f32x2 packed-FMA helpers (sm_103a) -------------------------
union U64F2 { unsigned long long u; float2 f2; };
union F4U2  { float4 f4; unsigned long long u2[2]; };

__device__ __forceinline__ unsigned long long fma2(unsigned long long a,
                                                   unsigned long long b,
                                                   unsigned long long c) {
    unsigned long long d;
    asm("fma.rn.f32x2 %0, %1, %2, %3;" : "=l"(d) : "l"(a), "l"(b), "l"(c));
    return d;
}
__device__ __forceinline__ unsigned long long splat2(float a) {
    unsigned long long r;
    asm("mov.b64 %0, {%1, %1};" : "=l"(r) : "f"(a));
    return r;
}
__device__ __forceinline__ void cp_async16(unsigned saddr, const void* gptr) {
    asm volatile("cp.async.cg.shared.global [%0], [%1], 16;"
                 :: "r"(saddr), "l"(gptr));
}

// ---------------- XLA-exact activations --------------------------------------
__device__ __forceinline__ float tanh_xla(float x) {
    const float ax = fabsf(x);
    float xc = fminf(fmaxf(x, -9.0f), 9.0f);
    float x2 = __fmul_rn(xc, xc);
    float p = -2.76076847742355e-16f;
    p = __fadd_rn(__fmul_rn(x2, p),  2.00018790482477e-13f);
    p = __fadd_rn(__fmul_rn(x2, p), -8.60467152213735e-11f);
    p = __fadd_rn(__fmul_rn(x2, p),  5.12229709037114e-08f);
    p = __fadd_rn(__fmul_rn(x2, p),  1.48572235717979e-05f);
    p = __fadd_rn(__fmul_rn(x2, p),  6.37261928875436e-04f);
    p = __fadd_rn(__fmul_rn(x2, p),  4.89352455891786e-03f);
    float num = __fmul_rn(xc, p);
    float q = 1.19825839466702e-06f;
    q = __fadd_rn(__fmul_rn(x2, q), 1.18534705686654e-04f);
    q = __fadd_rn(__fmul_rn(x2, q), 2.26843463243900e-03f);
    q = __fadd_rn(__fmul_rn(x2, q), 4.89352518554385e-03f);
    float r = __fdiv_rn(num, q);
    return (ax < 0.0004f) ? x : r;
}
__device__ __forceinline__ float sigmoid_xla(float x) {
    return __fadd_rn(0.5f, __fmul_rn(0.5f, tanh_xla(__fmul_rn(0.5f, x))));
}

// ---------------- init: reset spin-barrier counter every replay --------------
__global__ void init_kernel() { if (threadIdx.x == 0) g_bar = 0u; }
// dummy launch to shift the fixed ncu capture window onto lstm_kernel
__global__ void probe_kernel() { }

// ---------------- phase 1: fused embedding gather + input projection GEMM ----
// out[m][n] = emb[x[m]] . W[n][:]  (bias added in lstm). Packed f32x2 over
// output-column pairs: each accumulator's k-chain is bit-identical to scalar.
__global__ __launch_bounds__(256) void gemm_ih(const int* __restrict__ x,
                                               const float* __restrict__ emb,
                                               const float* __restrict__ wf,
                                               const float* __restrict__ wb) {
    __shared__ float As[16][64];
    __shared__ float Bs[16][64];
    __shared__ int   rix[64];
    const int dir = blockIdx.z;
    const float* __restrict__ W = dir ? wb : wf;
    float* __restrict__ Xout = g_X[dir];
    const int tid = threadIdx.x;
    const int m0 = blockIdx.y << 6, n0 = blockIdx.x << 6;

    if (tid < 64) rix[tid] = x[m0 + tid];
    __syncthreads();

    const int r  = tid & 63, kk = tid >> 6;       // loader: row r, k-quad kk
    const int tx = tid & 15, ty = tid >> 4;       // compute: 4x4 micro-tile
    const float* aptr = emb + (size_t)rix[r] * 256 + (kk << 2);
    const float* bptr = W   + (size_t)(n0 + r) * 256 + (kk << 2);

    unsigned long long acc[4][2];
#pragma unroll
    for (int i = 0; i < 4; ++i) { acc[i][0] = 0ull; acc[i][1] = 0ull; }

    for (int kt = 0; kt < 16; ++kt) {
        float4 a = *(const float4*)(aptr + (kt << 4));
        float4 b = *(const float4*)(bptr + (kt << 4));
        __syncthreads();
        As[(kk << 2) + 0][r] = a.x; As[(kk << 2) + 1][r] = a.y;
        As[(kk << 2) + 2][r] = a.z; As[(kk << 2) + 3][r] = a.w;
        Bs[(kk << 2) + 0][r] = b.x; Bs[(kk << 2) + 1][r] = b.y;
        Bs[(kk << 2) + 2][r] = b.z; Bs[(kk << 2) + 3][r] = b.w;
        __syncthreads();
#pragma unroll
        for (int k = 0; k < 16; ++k) {
            float4 av = *(const float4*)&As[k][ty << 2];
            F4U2 bu; bu.f4 = *(const float4*)&Bs[k][tx << 2];
            float ar[4] = {av.x, av.y, av.z, av.w};
#pragma unroll
            for (int i = 0; i < 4; ++i) {
                unsigned long long ai = splat2(ar[i]);
                acc[i][0] = fma2(ai, bu.u2[0], acc[i][0]);
                acc[i][1] = fma2(ai, bu.u2[1], acc[i][1]);
            }
        }
    }
#pragma unroll
    for (int i = 0; i < 4; ++i) {
        size_t m = (size_t)(m0 + (ty << 2) + i);
        U64F2 lo, hi; lo.u = acc[i][0]; hi.u = acc[i][1];
        float4 s = make_float4(lo.f2.x, lo.f2.y, hi.f2.x, hi.f2.y);
        *(float4*)(Xout + m * 2048 + n0 + (tx << 2)) = s;
    }
}

// ---------------- phase 2: persistent bidirectional LSTM ---------------------
// 128 blocks. dir = blk/64; block owns 8 hidden units u0 = (blk%64)*8.
// This round: xsm double-buffered, next step's X prefetch issued at the TOP of
// the current step (wait_group 1) so it has a whole step of latency headroom.
// Smem floats: Wsm 16384 | hsm 32768 | csm 512 | xsm 2*2304 | hnew 512 | msk 1024
#define LSTM_SMEM ((16384 + 32768 + 512 + 4608 + 512 + 1024) * 4)

__device__ __forceinline__ void grid_barrier(unsigned target) {
    __syncthreads();
    if (threadIdx.x == 0) {
        asm volatile("red.release.gpu.global.add.u32 [%0], %1;"
                     :: "l"(&g_bar), "r"(1u) : "memory");
        unsigned v;
        while (1) {
            asm volatile("ld.acquire.gpu.global.u32 %0, [%1];"
                         : "=r"(v) : "l"(&g_bar) : "memory");
            if (v >= target) break;
            __nanosleep(16);
        }
    }
    __syncthreads();
}

__global__ __launch_bounds__(256, 1) void lstm_kernel(const int* __restrict__ x,
                                                      const float* __restrict__ whh_f,
                                                      const float* __restrict__ whh_b,
                                                      const float* __restrict__ bias_f,
                                                      const float* __restrict__ bias_b) {
    extern __shared__ float sm[];
    float* Wsm  = sm;                      // 32*512
    float* hsm  = Wsm + 16384;             // packed [k4][b][4] (512*64 floats)
    float* csm  = hsm + 32768;             // 8*64   ([j*64+b])
    float* xsm  = csm + 512;               // 2 x 64*36 ([buf][b][gate*8+j])
    float* hnew = xsm + 4608;              // 8*64   ([j*64+b]) new carry bounce
    unsigned* msk = (unsigned*)(hnew + 512); // 64*16 bitmask words [b][t/32]

    const int tid = threadIdx.x;
    const int blk = blockIdx.x;
    const int dir = blk >> 6;
    const int u0  = (blk & 63) << 3;
    const int b   = tid & 63;
    const int p   = tid >> 6;              // 0..3; thread owns units p, p+4
    const float* __restrict__ Whh = dir ? whh_b : whh_f;
    const float* __restrict__ bia = dir ? bias_b : bias_f;
    const float* __restrict__ Xg  = g_X[dir];
    float* __restrict__ ring = g_h + dir * (3 * 512 * 64);
    const unsigned xsm_base = (unsigned)__cvta_generic_to_shared(xsm);

    // resident weights: local row lr = gate*8 + j  ->  w_hh[gate*512+u0+j][:]
    for (int i = tid; i < 32 * 128; i += 256) {     // float4 granules
        int lr = i >> 7, k4 = (i & 127) << 2;
        int gate = lr >> 3, j = lr & 7;
        float4 v = *(const float4*)&Whh[(size_t)(gate * 512 + u0 + j) * 512 + k4];
        *(float4*)&Wsm[lr * 512 + k4] = v;
    }
    float bb0[4], bb1[4];
#pragma unroll
    for (int g = 0; g < 4; ++g) {
        bb0[g] = bia[g * 512 + u0 + p];
        bb1[g] = bia[g * 512 + u0 + p + 4];
    }
    for (int i = tid; i < 512; i += 256) csm[i] = 0.f;
    // pad-mask bitmap: msk[b*16 + w] bit i = (x[b][w*32+i] != 0)
    for (int i = tid; i < 1024; i += 256) {
        int bb2 = i >> 4, w = i & 15;
        unsigned m = 0;
        for (int bit = 0; bit < 32; ++bit)
            m |= (x[bb2 * 512 + w * 32 + bit] != 0) ? (1u << bit) : 0u;
        msk[i] = m;
    }
    // zero ring buffer 0 for own units (packed [k4][b][4] layout)
    for (int i = tid; i < 512; i += 256) {
        int j = i >> 6, bb = i & 63, u = u0 + j;
        ring[((u >> 2) * 64 + bb) * 4 + (u & 3)] = 0.f;
    }

    // prefetch X gate-tile for step 0 into xsm buf 0
    {
        const int t0 = dir ? 511 : 0;
        int o = tid << 1;
#pragma unroll
        for (int q = 0; q < 2; ++q) {
            int bb2 = o >> 3, g = (o >> 1) & 3, hf = o & 1;
            const float* src = Xg + ((size_t)bb2 * 512 + t0) * 2048
                                  + g * 512 + u0 + hf * 4;
            cp_async16(xsm_base + (unsigned)(bb2 * 36 + g * 8 + hf * 4) * 4, src);
            ++o;
        }
        asm volatile("cp.async.commit_group;" ::: "memory");
    }
    unsigned nbar = 1;
    grid_barrier(nbar * NBLK);   // release publishes ring zeroing

    for (int s = 0; s < 512; ++s) {
        const int t  = dir ? 511 - s : s;
        const int rb = s % 3, wbuf = (s + 1) % 3;

        // issue NEXT step's X prefetch into the other xsm buffer, then wait
        // for THIS step's group (wait_group 1 leaves the new one in flight)
        if (s < 511) {
            const int tn = dir ? 510 - s : s + 1;
            const unsigned dstb = xsm_base + ((unsigned)((s + 1) & 1)) * 9216u;
            int o = tid << 1;
#pragma unroll
            for (int q = 0; q < 2; ++q) {
                int bb2 = o >> 3, g = (o >> 1) & 3, hf = o & 1;
                const float* src = Xg + ((size_t)bb2 * 512 + tn) * 2048
                                      + g * 512 + u0 + hf * 4;
                cp_async16(dstb + (unsigned)(bb2 * 36 + g * 8 + hf * 4) * 4, src);
                ++o;
            }
            asm volatile("cp.async.commit_group;" ::: "memory");
            asm volatile("cp.async.wait_group 1;" ::: "memory");
        } else {
            asm volatile("cp.async.wait_group 0;" ::: "memory");
        }
        __syncthreads();
        const float* xcur = xsm + (s & 1) * 2304;

        const float4* src4 = (const float4*)(ring + rb * 32768);
        float4* dst4 = (float4*)hsm;
        float4 rreg[8];
#pragma unroll
        for (int q = 0; q < 8; ++q) rreg[q] = __ldcg(src4 + tid + 256 * q);

        unsigned long long d0[4] = {0ull, 0ull, 0ull, 0ull};
        unsigned long long d1[4] = {0ull, 0ull, 0ull, 0ull};

        for (int c = 0; c < 4; ++c) {
#pragma unroll
            for (int q = 0; q < 8; ++q)
                dst4[c * 2048 + tid + 256 * q] = rreg[q];
            if (c < 3) {
#pragma unroll
                for (int q = 0; q < 8; ++q)
                    rreg[q] = __ldcg(src4 + (c + 1) * 2048 + tid + 256 * q);
            }
            __syncthreads();
            const int kbeg = c << 7;
#pragma unroll 4
            for (int k = kbeg; k < kbeg + 128; k += 4) {
                F4U2 h4; h4.f4 = *(const float4*)&hsm[((k >> 2) * 64 + b) * 4];
#pragma unroll
                for (int g = 0; g < 4; ++g) {
                    F4U2 w0; w0.f4 = *(const float4*)&Wsm[(g * 8 + p) * 512 + k];
                    d0[g] = fma2(h4.u2[0], w0.u2[0], d0[g]);
                    d0[g] = fma2(h4.u2[1], w0.u2[1], d0[g]);
                    F4U2 w1; w1.f4 = *(const float4*)&Wsm[(g * 8 + p + 4) * 512 + k];
                    d1[g] = fma2(h4.u2[0], w1.u2[0], d1[g]);
                    d1[g] = fma2(h4.u2[1], w1.u2[1], d1[g]);
                }
            }
        }

        const bool mk = (msk[b * 16 + (t >> 5)] >> (t & 31)) & 1u;
#pragma unroll
        for (int half = 0; half < 2; ++half) {
            const unsigned long long* dd = half ? d1 : d0;
            const float* bv = half ? bb1 : bb0;
            const int j = p + half * 4;
            const int u = u0 + j;
            U64F2 e0, e1, e2, e3;
            e0.u = dd[0]; e1.u = dd[1]; e2.u = dd[2]; e3.u = dd[3];
            float s0 = __fadd_rn(e0.f2.x, e0.f2.y);
            float s1 = __fadd_rn(e1.f2.x, e1.f2.y);
            float s2 = __fadd_rn(e2.f2.x, e2.f2.y);
            float s3 = __fadd_rn(e3.f2.x, e3.f2.y);
            float zi = __fadd_rn(__fadd_rn(xcur[b * 36 + 0 * 8 + j], s0), bv[0]);
            float zf = __fadd_rn(__fadd_rn(xcur[b * 36 + 1 * 8 + j], s1), bv[1]);
            float zg = __fadd_rn(__fadd_rn(xcur[b * 36 + 2 * 8 + j], s2), bv[2]);
            float zo = __fadd_rn(__fadd_rn(xcur[b * 36 + 3 * 8 + j], s3), bv[3]);
            float ii = sigmoid_xla(zi);
            float ff = sigmoid_xla(zf);
            float oo = sigmoid_xla(zo);
            float gg = tanh_xla(zg);
            float cold = csm[j * 64 + b];
            float cn = __fadd_rn(__fmul_rn(ff, cold), __fmul_rn(ii, gg));
            float hn = __fmul_rn(oo, tanh_xla(cn));
            float hold = hsm[((u >> 2) * 64 + b) * 4 + (u & 3)];
            float ck = mk ? cn : cold;
            float hk = mk ? hn : hold;
            csm[j * 64 + b] = ck;
            // coalesced store: [dir*512+u][t*64+b]
            g_hid[(size_t)(dir * 512 + u) * 32768 + t * 64 + b] = mk ? hn : 0.f;
            hnew[j * 64 + b] = hk;                 // smem bounce for ring
            if (s == 511) g_hT[b * 1024 + dir * 512 + u] = hk;
        }
        __syncthreads();
        // coalesced ring write: 128 threads sweep the block's 2KB carry slice
        if (tid < 128) {
            const int q = tid >> 6, bb2 = tid & 63;
            float4 v;
            v.x = hnew[(q * 4 + 0) * 64 + bb2];
            v.y = hnew[(q * 4 + 1) * 64 + bb2];
            v.z = hnew[(q * 4 + 2) * 64 + bb2];
            v.w = hnew[(q * 4 + 3) * 64 + bb2];
            *(float4*)&ring[wbuf * 32768 + (u0 >> 2) * 256 + tid * 4] = v;
        }
        ++nbar;
        grid_barrier(nbar * NBLK);   // release orders ring/g_hid stores
    }
}

// ---------------- phase 3: emissions = hid @ fc_w.T + fc_b -------------------
// 512 threads: (t,b) pair x k-half. Each half is a sequential FMA-Kahan chain
// (order-preserving); halves combined in fp64. 8-wide load batches -> MLP 8.
__global__ __launch_bounds__(512) void emis_kernel(const float* __restrict__ fcw,
                                                   const float* __restrict__ fcb) {
    __shared__ float smw[12 * 1024];
    __shared__ float part[256 * 24];
    const int tid = threadIdx.x;
    const int loc = tid & 255, kh = tid >> 8;
    const int tb  = blockIdx.x * 256 + loc;
    for (int i = tid; i < 12288; i += 512) smw[i] = fcw[i];
    __syncthreads();
    float s[12], c[12];
#pragma unroll
    for (int j = 0; j < 12; ++j) { s[j] = 0.f; c[j] = 0.f; }
    const int k0 = kh << 9;
    for (int k = k0; k < k0 + 512; k += 8) {
        float hv[8];
#pragma unroll
        for (int q = 0; q < 8; ++q)
            hv[q] = __ldcs(&g_hid[(size_t)(k + q) * 32768 + tb]);
#pragma unroll
        for (int q = 0; q < 8; ++q) {
#pragma unroll
            for (int j = 0; j < 12; ++j) {
                float y = __fmaf_rn(hv[q], smw[j * 1024 + k + q], -c[j]);
                float t = __fadd_rn(s[j], y);
                c[j] = __fsub_rn(__fsub_rn(t, s[j]), y);
                s[j] = t;
            }
        }
    }
    if (kh == 1) {
#pragma unroll
        for (int j = 0; j < 12; ++j) {
            part[loc * 24 + j]      = s[j];
            part[loc * 24 + 12 + j] = c[j];
        }
    }
    __syncthreads();
    if (kh == 0) {
#pragma unroll
        for (int j = 0; j < 12; ++j) {
            double acc = ((double)s[j] - (double)c[j])
                       + ((double)part[loc * 24 + j] - (double)part[loc * 24 + 12 + j]);
            g_emis[(size_t)tb * 12 + j] = __fadd_rn((float)acc, fcb[j]);
        }
    }
}

// ---------------- phase 4: class probs = softmax(hT @ fc2_w.T + fc2_b) -------
__global__ __launch_bounds__(32) void cls_kernel(const float* __restrict__ w2,
                                                 const float* __restrict__ b2,
                                                 float* __restrict__ out) {
    const int bb = blockIdx.x;
    const int lane = threadIdx.x;
    double acc[10];
#pragma unroll
    for (int j = 0; j < 10; ++j) acc[j] = 0.0;
    for (int k = lane; k < 1024; k += 32) {
        double hv = (double)g_hT[bb * 1024 + k];
#pragma unroll
        for (int j = 0; j < 10; ++j)
            acc[j] = fma(hv, (double)__ldg(&w2[j * 1024 + k]), acc[j]);
    }
#pragma unroll
    for (int j = 0; j < 10; ++j)
#pragma unroll
        for (int off = 16; off; off >>= 1)
            acc[j] += __shfl_down_sync(0xffffffffu, acc[j], off);
    if (lane == 0) {
        float z[10], mx = -1e30f, ssum = 0.f;
#pragma unroll
        for (int j = 0; j < 10; ++j) { z[j] = __fadd_rn((float)acc[j], b2[j]); mx = fmaxf(mx, z[j]); }
#pragma unroll
        for (int j = 0; j < 10; ++j) { z[j] = expf(z[j] - mx); ssum += z[j]; }
        float inv = 1.f / ssum;
#pragma unroll
        for (int j = 0; j < 10; ++j) out[64 + 32768 + bb * 10 + j] = z[j] * inv;
    }
}

// ---------------- phase 5: Viterbi — warp-synchronous, shfl-based ------------
__global__ __launch_bounds__(32) void vit_kernel(const int* __restrict__ x,
                                                 const float* __restrict__ trans,
                                                 float* __restrict__ out) {
    const int bb = blockIdx.x;
    const int lane = threadIdx.x;
    __shared__ float tr[144];
    __shared__ short bp[511][12];
    __shared__ short path[512];

    for (int i = lane; i < 144; i += 32) tr[i] = trans[i];
    __syncwarp();

    float tcol[12];
#pragma unroll
    for (int i = 0; i < 12; ++i) tcol[i] = (lane < 12) ? tr[i * 12 + lane] : 0.f;

    float alph = (lane < 12)
        ? __fadd_rn(tr[BOS * 12 + lane], g_emis[(size_t)(0 * 64 + bb) * 12 + lane])
        : -1e30f;

    float e_cur = (lane < 12) ? g_emis[(size_t)(1 * 64 + bb) * 12 + lane] : 0.f;
    int   v_cur = (x[bb * 512 + 1] != 0);

    for (int t = 1; t < 512; ++t) {
        float e_nxt = 0.f; int v_nxt = 0;
        if (t < 511) {
            e_nxt = (lane < 12) ? g_emis[(size_t)((t + 1) * 64 + bb) * 12 + lane] : 0.f;
            v_nxt = (x[bb * 512 + t + 1] != 0);
        }
        float best = -1e30f; int bi = 0;
#pragma unroll
        for (int i = 0; i < 12; ++i) {
            float ai = __shfl_sync(0xffffffffu, alph, i);
            float sc = __fadd_rn(ai, tcol[i]);
            if (sc > best) { best = sc; bi = i; }    // first-index tie-break
        }
        if (lane < 12) {
            alph = v_cur ? __fadd_rn(best, e_cur) : alph;
            bp[t - 1][lane] = v_cur ? (short)bi : (short)lane;
        }
        e_cur = e_nxt; v_cur = v_nxt;
    }
    __syncwarp();

    float fin = -1e30f;
    if (lane < 12) fin = __fadd_rn(alph, tr[lane * 12 + EOSx]);
    float best = -1e30f; int bt = 0;
#pragma unroll
    for (int i = 0; i < 12; ++i) {
        float fi = __shfl_sync(0xffffffffu, fin, i);
        if (fi > best) { best = fi; bt = i; }
    }
    if (lane == 0) {
        out[bb] = best;
        int tag = bt;
        for (int t = 511; t >= 1; --t) { path[t] = (short)tag; tag = bp[t - 1][tag]; }
        path[0] = (short)tag;
    }
    __syncwarp();
    for (int t = lane; t < 512; t += 32)
        out[64 + bb * 512 + t] = (x[bb * 512 + t] != 0) ? (float)path[t] : (float)PADTAG;
}

// ---------------- launcher ---------------------------------------------------
extern "C" void kernel_launch(void* const* d_in, const int* in_sizes, int n_in,
                              void* d_out, int out_size) {
    const int*   x      = (const int*)d_in[0];
    const float* emb    = (const float*)d_in[1];
    const float* w_ih_f = (const float*)d_in[2];
    const float* w_hh_f = (const float*)d_in[3];
    const float* b_f    = (const float*)d_in[4];
    const float* w_ih_b = (const float*)d_in[5];
    const float* w_hh_b = (const float*)d_in[6];
    const float* b_b    = (const float*)d_in[7];
    const float* fc_w   = (const float*)d_in[8];
    const float* fc_b   = (const float*)d_in[9];
    const float* fc2_w  = (const float*)d_in[10];
    const float* fc2_b  = (const float*)d_in[11];
    const float* trans  = (const float*)d_in[12];
    float* out = (float*)d_out;

    cudaFuncSetAttribute(lstm_kernel,
                         cudaFuncAttributeMaxDynamicSharedMemorySize, LSTM_SMEM);

    init_kernel<<<1, 32>>>();
    probe_kernel<<<1, 32>>>();   // shifts fixed ncu window onto lstm_kernel
    gemm_ih<<<dim3(32, 512, 2), 256>>>(x, emb, w_ih_f, w_ih_b);
    lstm_kernel<<<NBLK, 256, LSTM_SMEM>>>(x, w_hh_f, w_hh_b, b_f, b_b);
    emis_kernel<<<128, 512>>>(fc_w, fc_b);
    cls_kernel<<<64, 32>>>(fc2_w, fc2_b, out);
    vit_kernel<<<64, 32>>>(x, trans, out);
}